// round 12
// baseline (speedup 1.0000x reference)
#include <cuda_runtime.h>
#include <math.h>
#include <stdint.h>

#define THREADS   128
#define IMGS      128
#define NP        129                  // float4 stride per v-row (odd -> conflict-free)
#define PX_F4     (14 * NP)            // 1806 float4, single buffer
#define SMEM_BYTES (PX_F4 * 16)        // 28896 B

typedef unsigned long long ull;

// W repacked per k: cW2[k*3+0]=((W0,W1),(W2,W3)), [1]=((W4,W5),(W6,W7)), [2]=((W8,W9),pad)
__constant__ ulonglong2 cW2[784 * 3];
__constant__ float      cbias[10];
__device__   ull        g_wp[784 * 6];   // prep scratch

__device__ __forceinline__ void fma2(ull &acc, ull a, ull b) {
    asm("fma.rn.f32x2 %0, %1, %2, %0;" : "+l"(acc) : "l"(a), "l"(b));
}
__device__ __forceinline__ ull pack2(float lo, float hi) {
    ull r; asm("mov.b64 %0, {%1, %2};" : "=l"(r) : "f"(lo), "f"(hi)); return r;
}
__device__ __forceinline__ float2 unpack2(ull v) {
    float lo, hi; asm("mov.b64 {%0, %1}, %2;" : "=f"(lo), "=f"(hi) : "l"(v));
    return make_float2(lo, hi);
}

__global__ void prep_kernel(const float* __restrict__ W) {
    int i = blockIdx.x * blockDim.x + threadIdx.x;   // 0..4703
    if (i < 784 * 6) {
        int k = i / 6, oq = i - 6 * k;
        ull v = 0ull;
        if (oq < 5) {
            uint32_t lo = __float_as_uint(W[(2 * oq)     * 784 + k]);
            uint32_t hi = __float_as_uint(W[(2 * oq + 1) * 784 + k]);
            v = ((ull)hi << 32) | lo;
        }
        g_wp[i] = v;
    }
}

// one patch-row tile, two images (slots p, p+64), cols CB..CB+6
template<int CB>
__device__ __forceinline__ void compute_tile(const float4* __restrict__ px,
                                             int r, int p, ull* accA, ull* accB)
{
    #pragma unroll
    for (int cc = 0; cc < 7; cc++) {
        const int c  = CB + cc;          // compile-time
        const int vA = c >> 1;
        const int vB = 7 + vA;
        float4 a0 = px[vA * NP + p];
        float4 a1 = px[vA * NP + 64 + p];
        float4 b0 = px[vB * NP + p];
        float4 b1 = px[vB * NP + 64 + p];
        float x00_0, x01_0, x10_0, x11_0, x00_1, x01_1, x10_1, x11_1;
        if ((c & 1) == 0) {
            x00_0 = a0.x; x01_0 = a0.y; x10_0 = b0.x; x11_0 = b0.y;
            x00_1 = a1.x; x01_1 = a1.y; x10_1 = b1.x; x11_1 = b1.y;
        } else {
            x00_0 = a0.z; x01_0 = a0.w; x10_0 = b0.z; x11_0 = b0.w;
            x00_1 = a1.z; x01_1 = a1.w; x10_1 = b1.z; x11_1 = b1.w;
        }
        float ea[4], eb[4];
        ea[0] = __cosf(x00_0);
        ea[1] = ea[0] * __cosf(x01_0);
        ea[2] = ea[1] * __cosf(x10_0);
        ea[3] = ea[2] * __cosf(x11_0);
        eb[0] = __cosf(x00_1);
        eb[1] = eb[0] * __cosf(x01_1);
        eb[2] = eb[1] * __cosf(x10_1);
        eb[3] = eb[2] * __cosf(x11_1);

        const int kb3 = (r * 56 + c * 4) * 3;
        #pragma unroll
        for (int j = 0; j < 4; j++) {
            ulonglong2 w01 = cW2[kb3 + j * 3];       // uniform const (LDCU) loads
            ulonglong2 w23 = cW2[kb3 + j * 3 + 1];
            ulonglong2 w4p = cW2[kb3 + j * 3 + 2];
            ull da = pack2(ea[j], ea[j]);
            ull db = pack2(eb[j], eb[j]);
            fma2(accA[0], da, w01.x);
            fma2(accA[1], da, w01.y);
            fma2(accA[2], da, w23.x);
            fma2(accA[3], da, w23.y);
            fma2(accA[4], da, w4p.x);
            fma2(accB[0], db, w01.x);
            fma2(accB[1], db, w01.y);
            fma2(accB[2], db, w23.x);
            fma2(accB[3], db, w23.y);
            fma2(accB[4], db, w4p.x);
        }
    }
}

__global__ void __launch_bounds__(THREADS, 5)
quanv_kernel(const float* __restrict__ x, float* __restrict__ out)
{
    extern __shared__ float smem[];
    float4* s_px = (float4*)smem;    // [14][NP] float4, single buffer
    float*  s_mg = smem;             // epilogue merge aliases px buffer

    const int tid   = threadIdx.x;
    const int p     = tid & 63;      // image-pair slot (imgs 2p, 2p+1)
    const int chalf = tid >> 6;      // 0: cols 0..6, 1: cols 7..13 (warp-uniform)

    const long imgBase = (long)blockIdx.x * IMGS;
    const float* xg = x + imgBase * 784;

    // granule base (j = tid + 128*it): img = j/14, v = j%14.
    // Half A = it 0..6; half B = it 7..13 == half A with img+64
    // (gmem offset +50176 floats, slot pos +32).
    const int v0   = tid % 14;
    const int img0 = tid / 14;
    const int off0 = img0 * 784 + v0 * 4;

    // prefetch half A of tile 0 (7 float4)
    float4 stage[7];
    {
        int v = v0, off = off0;
        #pragma unroll
        for (int it = 0; it < 7; it++) {
            stage[it] = *(const float4*)(xg + off);
            off += 7064; v += 2;                 // j += 128
            if (v >= 14) { v -= 14; off += 728; }
        }
    }

    ull accA[5], accB[5];
    #pragma unroll
    for (int q = 0; q < 5; q++) { accA[q] = 0ull; accB[q] = 0ull; }

    #pragma unroll 1
    for (int r = 0; r < 14; r++) {
        // 1) store half A (prefetched)
        {
            int v = v0, img = img0;
            #pragma unroll
            for (int it = 0; it < 7; it++) {
                int pos = ((img & 1) << 6) | (img >> 1);
                s_px[v * NP + pos] = stage[it];
                v += 2; img += 9;
                if (v >= 14) { v -= 14; img++; }
            }
        }
        // 2) load + store half B of tile r (latency covered by other warps/CTAs)
        {
            const float* srcB = xg + r * 56 + 50176;
            int v = v0, img = img0, off = off0;
            #pragma unroll
            for (int it = 0; it < 7; it++) stage[it] = *(const float4*)(srcB + ((it == 0) ? off : (off = ((v += 2) >= 14 ? (v -= 14, off + 7792) : off + 7064))));
            v = v0; img = img0;
            #pragma unroll
            for (int it = 0; it < 7; it++) {
                int pos = (((img & 1) << 6) | (img >> 1)) + 32;
                s_px[v * NP + pos] = stage[it];
                v += 2; img += 9;
                if (v >= 14) { v -= 14; img++; }
            }
        }
        __syncthreads();

        // 3) prefetch half A of tile r+1 (hidden behind compute)
        if (r < 13) {
            const float* srcT = xg + (r + 1) * 56;
            int v = v0, off = off0;
            #pragma unroll
            for (int it = 0; it < 7; it++) {
                stage[it] = *(const float4*)(srcT + off);
                off += 7064; v += 2;
                if (v >= 14) { v -= 14; off += 728; }
            }
        }

        if (chalf == 0) compute_tile<0>(s_px, r, p, accA, accB);
        else            compute_tile<7>(s_px, r, p, accA, accB);
        __syncthreads();
    }

    // unpack o-pair accumulators
    float sA[10], sB[10];
    #pragma unroll
    for (int q = 0; q < 5; q++) {
        float2 fa = unpack2(accA[q]); sA[2 * q] = fa.x; sA[2 * q + 1] = fa.y;
        float2 fb = unpack2(accB[q]); sB[2 * q] = fb.x; sB[2 * q + 1] = fb.y;
    }

    // merge the two column-halves via shared (stride 21 per image slot)
    if (chalf == 1) {
        #pragma unroll
        for (int o = 0; o < 10; o++) {
            s_mg[p * 42 + o]      = sA[o];
            s_mg[p * 42 + 21 + o] = sB[o];
        }
    }
    __syncthreads();

    if (chalf == 0) {
        float l[20];
        #pragma unroll
        for (int o = 0; o < 10; o++) {
            l[o]      = sA[o] + s_mg[p * 42 + o]      + cbias[o];
            l[10 + o] = sB[o] + s_mg[p * 42 + 21 + o] + cbias[o];
        }
        #pragma unroll
        for (int im = 0; im < 2; im++) {
            float m = -INFINITY;
            #pragma unroll
            for (int o = 0; o < 10; o++) m = fmaxf(m, l[im * 10 + o]);
            float s = 0.f;
            #pragma unroll
            for (int o = 0; o < 10; o++) s += __expf(l[im * 10 + o] - m);
            float lse = m + __logf(s);
            #pragma unroll
            for (int o = 0; o < 10; o++) l[im * 10 + o] -= lse;
        }
        float4* op = (float4*)(out + (imgBase + 2 * p) * 10);
        #pragma unroll
        for (int q = 0; q < 5; q++)
            op[q] = make_float4(l[q * 4], l[q * 4 + 1], l[q * 4 + 2], l[q * 4 + 3]);
    }
}

extern "C" void kernel_launch(void* const* d_in, const int* in_sizes, int n_in,
                              void* d_out, int out_size)
{
    const float* x = (const float*)d_in[0];
    const float* W = (const float*)d_in[1];
    const float* b = (const float*)d_in[2];
    float* out = (float*)d_out;

    prep_kernel<<<19, 256>>>(W);

    void* wp_addr = nullptr;
    cudaGetSymbolAddress(&wp_addr, g_wp);
    cudaMemcpyToSymbolAsync(cW2, wp_addr, 784 * 6 * sizeof(ull), 0,
                            cudaMemcpyDeviceToDevice, 0);
    cudaMemcpyToSymbolAsync(cbias, b, 10 * sizeof(float), 0,
                            cudaMemcpyDeviceToDevice, 0);

    const int B = in_sizes[0] / 784;    // 65536
    const int grid = B / IMGS;          // 512 (<= 740 slots at 5 CTAs/SM: one wave)

    cudaFuncSetAttribute(quanv_kernel,
                         cudaFuncAttributeMaxDynamicSharedMemorySize, SMEM_BYTES);
    quanv_kernel<<<grid, THREADS, SMEM_BYTES>>>(x, out);
}